// round 15
// baseline (speedup 1.0000x reference)
#include <cuda_runtime.h>
#include <cuda_bf16.h>
#include <cstdint>

// ---------------------------------------------------------------------------
// Causal MHA: B=4, S=2048, D=1024, H=16, Dh=64.  fp32 in/out.
// All GEMMs: bf16x3 hi/lo split on mma.sync m16n8k16 (fp32-grade accuracy).
// This round: proj warp tile 16x64 (CTA 128x64, 8 warps) -> 3 CTAs/SM
// (24 warps/SM) for latency hiding.  MMA orders = R12 (known spill-free).
// ---------------------------------------------------------------------------

#define DEV_INLINE __device__ __forceinline__

static constexpr int BATCH = 4;
static constexpr int SEQ   = 2048;
static constexpr int DMODEL = 1024;
static constexpr int HEADS = 16;
static constexpr int HDIM  = 64;
static constexpr int MROWS = BATCH * SEQ;          // 8192
static constexpr int KW    = DMODEL / 2;           // 512 packed words per row

// ---- scratch (__device__ globals; no cudaMalloc allowed) ----
__device__ unsigned g_xh[MROWS * KW], g_xl[MROWS * KW];
__device__ unsigned g_wqh[DMODEL * KW], g_wql[DMODEL * KW];
__device__ unsigned g_wkh[DMODEL * KW], g_wkl[DMODEL * KW];
__device__ unsigned g_wvh[DMODEL * KW], g_wvl[DMODEL * KW];
__device__ unsigned g_woh[DMODEL * KW], g_wol[DMODEL * KW];
// Q,K packed [bh][s][32 words] (Q has 0.125 baked in)
__device__ unsigned g_Qh[64 * SEQ * 32], g_Ql[64 * SEQ * 32];
__device__ unsigned g_Kh[64 * SEQ * 32], g_Kl[64 * SEQ * 32];
// V transposed [bh][dh][s] bf16 (word view: SEQ/2 words per dh-row)
__device__ unsigned g_Vth[64 * HDIM * (SEQ / 2)], g_Vtl[64 * HDIM * (SEQ / 2)];
// attention out, packed hi/lo [b*2048+s][512 words]
__device__ unsigned g_AOh[MROWS * KW], g_AOl[MROWS * KW];

// ---------------------------------------------------------------------------
// helpers
// ---------------------------------------------------------------------------
DEV_INLINE unsigned pack2(float x0, float x1) {   // x0 -> low half
    unsigned r;
    asm("cvt.rn.bf16x2.f32 %0, %1, %2;" : "=r"(r) : "f"(x1), "f"(x0));
    return r;
}
DEV_INLINE void split_pack(float x0, float x1, unsigned& wh, unsigned& wl) {
    wh = pack2(x0, x1);
    float h0 = __uint_as_float(wh << 16);
    float h1 = __uint_as_float(wh & 0xffff0000u);
    wl = pack2(x0 - h0, x1 - h1);
}
DEV_INLINE unsigned cvta_s(const void* p) {
    return (unsigned)__cvta_generic_to_shared(p);
}
DEV_INLINE void ldsm4(unsigned& r0, unsigned& r1, unsigned& r2, unsigned& r3,
                      unsigned addr) {
    asm volatile("ldmatrix.sync.aligned.m8n8.x4.shared.b16 {%0,%1,%2,%3}, [%4];"
                 : "=r"(r0), "=r"(r1), "=r"(r2), "=r"(r3) : "r"(addr));
}
DEV_INLINE void mma16(float* d,
                      unsigned a0, unsigned a1, unsigned a2, unsigned a3,
                      unsigned b0, unsigned b1) {
    asm volatile(
        "mma.sync.aligned.m16n8k16.row.col.f32.bf16.bf16.f32 "
        "{%0,%1,%2,%3},{%4,%5,%6,%7},{%8,%9},{%0,%1,%2,%3};\n"
        : "+f"(d[0]), "+f"(d[1]), "+f"(d[2]), "+f"(d[3])
        : "r"(a0), "r"(a1), "r"(a2), "r"(a3), "r"(b0), "r"(b1));
}
DEV_INLINE void cp16(unsigned dst_s, const void* src) {
    asm volatile("cp.async.cg.shared.global [%0], [%1], 16;"
                 :: "r"(dst_s), "l"(src));
}
DEV_INLINE void cp_commit() { asm volatile("cp.async.commit_group;"); }
template <int N> DEV_INLINE void cp_wait() {
    asm volatile("cp.async.wait_group %0;" :: "n"(N));
}

// ---------------------------------------------------------------------------
// Convert: fp32 -> packed bf16 hi/lo words
// ---------------------------------------------------------------------------
__global__ void convert_kernel(const float2* __restrict__ src,
                               unsigned* __restrict__ hi,
                               unsigned* __restrict__ lo, int nwords) {
    int i = blockIdx.x * blockDim.x + threadIdx.x;
    if (i < nwords) {
        float2 v = src[i];
        unsigned wh, wl;
        split_pack(v.x, v.y, wh, wl);
        hi[i] = wh;
        lo[i] = wl;
    }
}

// ---------------------------------------------------------------------------
// Projection GEMM: out[m][n] = sum_k A[m][k] * W[n][k]   (preconverted inputs)
// CTA 128x64, BK=32, 8 warps (8x1, warp tile 16x64), bf16x3.
// 2-stage cp.async pipeline.  3 CTAs/SM (24 warps/SM).
// mode 0: fp32 [m][1024];  mode 1: packed hi/lo [bh][s][32w] (*scale);
// mode 2: V transposed bf16 hi/lo [bh][dh][s].
// ---------------------------------------------------------------------------
static constexpr int P_PW   = 20;                      // padded words / 16w row
static constexpr int P_ABUF = 128 * P_PW;              // 2560 words (Ah or Al)
static constexpr int P_BBUF = 64 * P_PW;               // 1280 words (Bh or Bl)
static constexpr int P_STG  = 2 * P_ABUF + 2 * P_BBUF; // 7680 words per stage
static constexpr int PROJ_SMEM_BYTES = 2 * P_STG * 4;  // 61440

__global__ __launch_bounds__(256, 3)
void proj_kernel(const unsigned* __restrict__ Ahg, const unsigned* __restrict__ Alg,
                 const unsigned* __restrict__ Bhg, const unsigned* __restrict__ Blg,
                 float* __restrict__ dst_f,
                 unsigned* __restrict__ dst_hi, unsigned* __restrict__ dst_lo,
                 int mode, float scale) {
    extern __shared__ unsigned smw[];
    const unsigned smB = cvta_s(smw);

    const int m0 = blockIdx.x * 128;
    const int n0 = blockIdx.y * 64;
    const int tid = threadIdx.x;
    const int warp = tid >> 5, lane = tid & 31;

    const int a_row_off  = (lane & 7) + ((lane >> 3) & 1) * 8;
    const int a_word_off = ((lane >> 4) & 1) * 4;
    const int b_row_off  = (lane & 7) + ((lane >> 4) & 1) * 8;
    const int b_word_off = ((lane >> 3) & 1) * 4;

    const unsigned aOff = ((warp * 16 + a_row_off) * P_PW + a_word_off) * 4u;
    unsigned bOff[4];
#pragma unroll
    for (int p = 0; p < 4; p++)
        bOff[p] = ((p * 16 + b_row_off) * P_PW + b_word_off) * 4u;

    float acc[8][4];
#pragma unroll
    for (int ni = 0; ni < 8; ni++)
#pragma unroll
        for (int j = 0; j < 4; j++) acc[ni][j] = 0.0f;

    // load one stage: 1536 x 16B chunks, 6 per thread
    auto prefetch = [&](int kt, int st) {
        unsigned base = (unsigned)(st * P_STG);
        int kw = kt * 16;
#pragma unroll
        for (int i = 0; i < 4; i++) {                 // A: ids 0..1023
            int id = tid + i * 256;
            int buf = id >> 9;                        // 0:Ah 1:Al
            int ch = id & 511;
            int row = ch >> 2, w = (ch & 3) * 4;
            const unsigned* src = (buf ? Alg : Ahg) + (size_t)(m0 + row) * KW + kw + w;
            cp16(smB + (base + (unsigned)buf * P_ABUF + row * P_PW + w) * 4u, src);
        }
#pragma unroll
        for (int i = 4; i < 6; i++) {                 // B: ids 1024..1535
            int id = tid + i * 256 - 1024;
            int buf = id >> 8;                        // 0:Bh 1:Bl
            int ch = id & 255;
            int row = ch >> 2, w = (ch & 3) * 4;
            const unsigned* src = (buf ? Blg : Bhg) + (size_t)(n0 + row) * KW + kw + w;
            cp16(smB + (base + 2u * P_ABUF + (unsigned)buf * P_BBUF +
                        row * P_PW + w) * 4u, src);
        }
    };

    prefetch(0, 0);
    cp_commit();

    for (int kt = 0; kt < 32; kt++) {
        const int st = kt & 1;
        cp_wait<0>();
        __syncthreads();                 // all warps done with stage st^1
        if (kt + 1 < 32) {
            prefetch(kt + 1, st ^ 1);    // safe: st^1 fully consumed
            cp_commit();
        }

        unsigned stB = smB + (unsigned)(st * P_STG) * 4u;
#pragma unroll
        for (int kk = 0; kk < 2; kk++) {
            unsigned ah0, ah1, ah2, ah3, al0, al1, al2, al3;
            ldsm4(ah0, ah1, ah2, ah3, stB + aOff + kk * 32u);
            ldsm4(al0, al1, al2, al3,
                  stB + (unsigned)P_ABUF * 4u + aOff + kk * 32u);
#pragma unroll
            for (int p = 0; p < 4; p++) {
                unsigned bh0, bh1, bh2, bh3, bl0, bl1, bl2, bl3;
                ldsm4(bh0, bh1, bh2, bh3,
                      stB + 2u * P_ABUF * 4u + bOff[p] + kk * 32u);
                ldsm4(bl0, bl1, bl2, bl3,
                      stB + (2u * P_ABUF + P_BBUF) * 4u + bOff[p] + kk * 32u);
                // R12-style ordering (known spill-free)
                mma16(acc[2 * p],     ah0, ah1, ah2, ah3, bh0, bh1);
                mma16(acc[2 * p],     al0, al1, al2, al3, bh0, bh1);
                mma16(acc[2 * p],     ah0, ah1, ah2, ah3, bl0, bl1);
                mma16(acc[2 * p + 1], ah0, ah1, ah2, ah3, bh2, bh3);
                mma16(acc[2 * p + 1], al0, al1, al2, al3, bh2, bh3);
                mma16(acc[2 * p + 1], ah0, ah1, ah2, ah3, bl2, bl3);
            }
        }
    }

    // ---- epilogue: warp owns rows [m0+warp*16, +16), cols [n0, n0+64) ----
#pragma unroll
    for (int ni = 0; ni < 8; ni++) {
        int r0 = m0 + warp * 16 + (lane >> 2);
        int r1 = r0 + 8;
        int c0 = n0 + ni * 8 + 2 * (lane & 3);
        if (mode == 0) {
            dst_f[(size_t)r0 * DMODEL + c0]     = acc[ni][0];
            dst_f[(size_t)r0 * DMODEL + c0 + 1] = acc[ni][1];
            dst_f[(size_t)r1 * DMODEL + c0]     = acc[ni][2];
            dst_f[(size_t)r1 * DMODEL + c0 + 1] = acc[ni][3];
        } else if (mode == 1) {
            int h = c0 >> 6, dhw = (c0 & 63) >> 1;
            unsigned wh, wl;
            {
                int b = r0 >> 11, s = r0 & 2047;
                size_t idx = ((size_t)(b * HEADS + h) * SEQ + s) * 32 + dhw;
                split_pack(acc[ni][0] * scale, acc[ni][1] * scale, wh, wl);
                dst_hi[idx] = wh; dst_lo[idx] = wl;
            }
            {
                int b = r1 >> 11, s = r1 & 2047;
                size_t idx = ((size_t)(b * HEADS + h) * SEQ + s) * 32 + dhw;
                split_pack(acc[ni][2] * scale, acc[ni][3] * scale, wh, wl);
                dst_hi[idx] = wh; dst_lo[idx] = wl;
            }
        } else {
            __nv_bfloat16* vh = reinterpret_cast<__nv_bfloat16*>(dst_hi);
            __nv_bfloat16* vl = reinterpret_cast<__nv_bfloat16*>(dst_lo);
#pragma unroll
            for (int e = 0; e < 4; e++) {
                int r = (e < 2) ? r0 : r1;
                int c = c0 + (e & 1);
                float v = acc[ni][e];
                int b = r >> 11, s = r & 2047;
                int h = c >> 6, dh = c & 63;
                size_t idx = ((size_t)(b * HEADS + h) * HDIM + dh) * SEQ + s;
                __nv_bfloat16 hb = __float2bfloat16(v);
                vh[idx] = hb;
                vl[idx] = __float2bfloat16(v - __bfloat162float(hb));
            }
        }
    }
}

// ---------------------------------------------------------------------------
// Flash attention: CTA = (64-row q tile, head, batch), 4 warps, 3 CTAs/SM.
// Score: bf16x3 k16.  PV: bf16x3 k16, P-frags from regs.  Writes packed AO.
// MMA ordering identical to R12 (known-good).
// ---------------------------------------------------------------------------
static constexpr int A_PW = 36;
static constexpr int AT_Q = 0;
static constexpr int AT_K = 4608;
static constexpr int AT_V = 13824;
static constexpr int ATTN_SMEM_BYTES = 18432 * 4;    // 73728

__global__ __launch_bounds__(128, 3)
void attn_kernel() {
    extern __shared__ unsigned smw[];
    const unsigned smB = cvta_s(smw);

    const int qt = (int)(gridDim.x - 1) - (int)blockIdx.x;
    const int h = blockIdx.y;
    const int b = blockIdx.z;
    const int bh = b * HEADS + h;
    const int q0 = qt * 64;

    const int tid = threadIdx.x;
    const int warp = tid >> 5;
    const int lane = tid & 31;

    const int a_row_off  = (lane & 7) + ((lane >> 3) & 1) * 8;
    const int a_word_off = ((lane >> 4) & 1) * 4;
    const int b_row_off  = (lane & 7) + ((lane >> 4) & 1) * 8;
    const int b_word_off = ((lane >> 3) & 1) * 4;

    const unsigned qOff = ((16 * warp + a_row_off) * A_PW + a_word_off) * 4u;
    unsigned kOff[4];
#pragma unroll
    for (int p = 0; p < 4; p++)
        kOff[p] = ((p * 16 + b_row_off) * A_PW + b_word_off) * 4u;

    auto issueQ = [&]() {
#pragma unroll
        for (int i = 0; i < 8; i++) {
            int ch = tid + i * 128;
            int row = ch >> 4, sub = ch & 15;
            int buf = sub >> 3, w = (sub & 7) * 4;
            const unsigned* src = (buf ? g_Ql : g_Qh) +
                                  ((size_t)bh * SEQ + q0 + row) * 32 + w;
            cp16(smB + (AT_Q + (unsigned)buf * 2304u + row * A_PW + w) * 4u, src);
        }
    };
    auto issueK = [&](int j, int st) {
#pragma unroll
        for (int i = 0; i < 8; i++) {
            int ch = tid + i * 128;
            int row = ch >> 4, sub = ch & 15;
            int buf = sub >> 3, w = (sub & 7) * 4;
            const unsigned* src = (buf ? g_Kl : g_Kh) +
                                  ((size_t)bh * SEQ + j * 64 + row) * 32 + w;
            cp16(smB + (AT_K + (unsigned)st * 4608u + (unsigned)buf * 2304u +
                        row * A_PW + w) * 4u, src);
        }
    };
    auto issueV = [&](int j) {
#pragma unroll
        for (int i = 0; i < 8; i++) {
            int ch = tid + i * 128;
            int row = ch >> 4, sub = ch & 15;
            int buf = sub >> 3, w = (sub & 7) * 4;
            const unsigned* src = (buf ? g_Vtl : g_Vth) +
                                  ((size_t)bh * HDIM + row) * (SEQ / 2) + j * 32 + w;
            cp16(smB + (AT_V + (unsigned)buf * 2304u + row * A_PW + w) * 4u, src);
        }
    };

    issueQ();
    issueK(0, 0);
    cp_commit();

    const float NEG = -1e30f;
    float mr0 = NEG, mr1 = NEG, l0 = 0.0f, l1 = 0.0f;
    float o[8][4];
#pragma unroll
    for (int nc = 0; nc < 8; nc++)
#pragma unroll
        for (int j = 0; j < 4; j++) o[nc][j] = 0.0f;

    const unsigned QhB = smB + AT_Q * 4u, QlB = QhB + 2304u * 4u;
    const unsigned VhB = smB + AT_V * 4u, VlB = VhB + 2304u * 4u;

    for (int j = 0; j <= qt; j++) {
        const int st = j & 1;
        const bool more = (j < qt);

        issueV(j);
        cp_commit();
        if (more) {
            issueK(j + 1, st ^ 1);
            cp_commit();
            cp_wait<2>();
        } else {
            cp_wait<1>();
        }
        __syncthreads();

        const unsigned KhB = smB + (AT_K + (unsigned)st * 4608u) * 4u;
        const unsigned KlB = KhB + 2304u * 4u;

        float s[8][4];
#pragma unroll
        for (int nc = 0; nc < 8; nc++)
#pragma unroll
            for (int e = 0; e < 4; e++) s[nc][e] = 0.0f;

#pragma unroll
        for (int kk = 0; kk < 4; kk++) {
            unsigned ah0, ah1, ah2, ah3, al0, al1, al2, al3;
            ldsm4(ah0, ah1, ah2, ah3, QhB + qOff + kk * 32u);
            ldsm4(al0, al1, al2, al3, QlB + qOff + kk * 32u);
#pragma unroll
            for (int p = 0; p < 4; p++) {
                unsigned kh0, kh1, kh2, kh3, kl0, kl1, kl2, kl3;
                ldsm4(kh0, kh1, kh2, kh3, KhB + kOff[p] + kk * 32u);
                ldsm4(kl0, kl1, kl2, kl3, KlB + kOff[p] + kk * 32u);
                mma16(s[2 * p],     ah0, ah1, ah2, ah3, kh0, kh1);
                mma16(s[2 * p],     al0, al1, al2, al3, kh0, kh1);
                mma16(s[2 * p],     ah0, ah1, ah2, ah3, kl0, kl1);
                mma16(s[2 * p + 1], ah0, ah1, ah2, ah3, kh2, kh3);
                mma16(s[2 * p + 1], al0, al1, al2, al3, kh2, kh3);
                mma16(s[2 * p + 1], ah0, ah1, ah2, ah3, kl2, kl3);
            }
        }

        if (j == qt) {
            int r0 = 16 * warp + (lane >> 2), r1 = r0 + 8;
#pragma unroll
            for (int nc = 0; nc < 8; nc++) {
                int c0 = nc * 8 + 2 * (lane & 3), c1 = c0 + 1;
                if (c0 > r0) s[nc][0] = NEG;
                if (c1 > r0) s[nc][1] = NEG;
                if (c0 > r1) s[nc][2] = NEG;
                if (c1 > r1) s[nc][3] = NEG;
            }
        }

        float pm0 = NEG, pm1 = NEG;
#pragma unroll
        for (int nc = 0; nc < 8; nc++) {
            pm0 = fmaxf(pm0, fmaxf(s[nc][0], s[nc][1]));
            pm1 = fmaxf(pm1, fmaxf(s[nc][2], s[nc][3]));
        }
        pm0 = fmaxf(pm0, __shfl_xor_sync(0xffffffffu, pm0, 1));
        pm0 = fmaxf(pm0, __shfl_xor_sync(0xffffffffu, pm0, 2));
        pm1 = fmaxf(pm1, __shfl_xor_sync(0xffffffffu, pm1, 1));
        pm1 = fmaxf(pm1, __shfl_xor_sync(0xffffffffu, pm1, 2));

        float mn0 = fmaxf(mr0, pm0), mn1 = fmaxf(mr1, pm1);
        float al0 = __expf(mr0 - mn0), al1 = __expf(mr1 - mn1);
        l0 *= al0;
        l1 *= al1;

        float rs0 = 0.0f, rs1 = 0.0f;
#pragma unroll
        for (int nc = 0; nc < 8; nc++) {
            s[nc][0] = __expf(s[nc][0] - mn0);
            s[nc][1] = __expf(s[nc][1] - mn0);
            s[nc][2] = __expf(s[nc][2] - mn1);
            s[nc][3] = __expf(s[nc][3] - mn1);
            rs0 += s[nc][0] + s[nc][1];
            rs1 += s[nc][2] + s[nc][3];
            o[nc][0] *= al0; o[nc][1] *= al0;
            o[nc][2] *= al1; o[nc][3] *= al1;
        }
        rs0 += __shfl_xor_sync(0xffffffffu, rs0, 1);
        rs0 += __shfl_xor_sync(0xffffffffu, rs0, 2);
        rs1 += __shfl_xor_sync(0xffffffffu, rs1, 1);
        rs1 += __shfl_xor_sync(0xffffffffu, rs1, 2);
        l0 += rs0;
        l1 += rs1;
        mr0 = mn0;
        mr1 = mn1;

        if (more) cp_wait<1>(); else cp_wait<0>();
        __syncthreads();

#pragma unroll
        for (int kc = 0; kc < 4; kc++) {
            unsigned pah[4], pal[4];
            split_pack(s[2 * kc][0],     s[2 * kc][1],     pah[0], pal[0]);
            split_pack(s[2 * kc][2],     s[2 * kc][3],     pah[1], pal[1]);
            split_pack(s[2 * kc + 1][0], s[2 * kc + 1][1], pah[2], pal[2]);
            split_pack(s[2 * kc + 1][2], s[2 * kc + 1][3], pah[3], pal[3]);
#pragma unroll
            for (int p = 0; p < 4; p++) {
                unsigned vh0, vh1, vh2, vh3, vl0, vl1, vl2, vl3;
                ldsm4(vh0, vh1, vh2, vh3, VhB + kOff[p] + kc * 32u);
                ldsm4(vl0, vl1, vl2, vl3, VlB + kOff[p] + kc * 32u);
                mma16(o[2 * p],     pah[0], pah[1], pah[2], pah[3], vh0, vh1);
                mma16(o[2 * p],     pal[0], pal[1], pal[2], pal[3], vh0, vh1);
                mma16(o[2 * p],     pah[0], pah[1], pah[2], pah[3], vl0, vl1);
                mma16(o[2 * p + 1], pah[0], pah[1], pah[2], pah[3], vh2, vh3);
                mma16(o[2 * p + 1], pal[0], pal[1], pal[2], pal[3], vh2, vh3);
                mma16(o[2 * p + 1], pah[0], pah[1], pah[2], pah[3], vl2, vl3);
            }
        }
        __syncthreads();
    }

    // epilogue: normalize, write packed AO hi/lo [b*2048+s][512]
    float inv0 = 1.0f / l0, inv1 = 1.0f / l1;
    int r0g = q0 + 16 * warp + (lane >> 2);
    int r1g = r0g + 8;
#pragma unroll
    for (int nc = 0; nc < 8; nc++) {
        int col = h * HDIM + nc * 8 + 2 * (lane & 3);
        unsigned wh, wl;
        size_t i0 = ((size_t)(b * SEQ + r0g)) * KW + (col >> 1);
        split_pack(o[nc][0] * inv0, o[nc][1] * inv0, wh, wl);
        g_AOh[i0] = wh; g_AOl[i0] = wl;
        size_t i1 = ((size_t)(b * SEQ + r1g)) * KW + (col >> 1);
        split_pack(o[nc][2] * inv1, o[nc][3] * inv1, wh, wl);
        g_AOh[i1] = wh; g_AOl[i1] = wl;
    }
}

// ---------------------------------------------------------------------------
extern "C" void kernel_launch(void* const* d_in, const int* in_sizes, int n_in,
                              void* d_out, int out_size) {
    const float* x  = (const float*)d_in[0];
    const float* wq = (const float*)d_in[1];
    const float* wk = (const float*)d_in[2];
    const float* wv = (const float*)d_in[3];
    const float* wo = (const float*)d_in[4];

    unsigned *xh, *xl, *wqh, *wql, *wkh, *wkl, *wvh, *wvl, *woh, *wol;
    unsigned *qh, *ql, *kh, *kl, *vth, *vtl, *aoh, *aol;
    cudaGetSymbolAddress((void**)&xh,  g_xh);  cudaGetSymbolAddress((void**)&xl,  g_xl);
    cudaGetSymbolAddress((void**)&wqh, g_wqh); cudaGetSymbolAddress((void**)&wql, g_wql);
    cudaGetSymbolAddress((void**)&wkh, g_wkh); cudaGetSymbolAddress((void**)&wkl, g_wkl);
    cudaGetSymbolAddress((void**)&wvh, g_wvh); cudaGetSymbolAddress((void**)&wvl, g_wvl);
    cudaGetSymbolAddress((void**)&woh, g_woh); cudaGetSymbolAddress((void**)&wol, g_wol);
    cudaGetSymbolAddress((void**)&qh,  g_Qh);  cudaGetSymbolAddress((void**)&ql,  g_Ql);
    cudaGetSymbolAddress((void**)&kh,  g_Kh);  cudaGetSymbolAddress((void**)&kl,  g_Kl);
    cudaGetSymbolAddress((void**)&vth, g_Vth); cudaGetSymbolAddress((void**)&vtl, g_Vtl);
    cudaGetSymbolAddress((void**)&aoh, g_AOh); cudaGetSymbolAddress((void**)&aol, g_AOl);

    cudaFuncSetAttribute(proj_kernel, cudaFuncAttributeMaxDynamicSharedMemorySize,
                         PROJ_SMEM_BYTES);
    cudaFuncSetAttribute(attn_kernel, cudaFuncAttributeMaxDynamicSharedMemorySize,
                         ATTN_SMEM_BYTES);

    const int NW_X = MROWS * KW;        // 4194304
    const int NW_W = DMODEL * KW;       // 524288
    convert_kernel<<<NW_X / 256, 256>>>((const float2*)x,  xh,  xl,  NW_X);
    convert_kernel<<<NW_W / 256, 256>>>((const float2*)wq, wqh, wql, NW_W);
    convert_kernel<<<NW_W / 256, 256>>>((const float2*)wk, wkh, wkl, NW_W);
    convert_kernel<<<NW_W / 256, 256>>>((const float2*)wv, wvh, wvl, NW_W);
    convert_kernel<<<NW_W / 256, 256>>>((const float2*)wo, woh, wol, NW_W);

    dim3 pgrid(MROWS / 128, DMODEL / 64);    // (64, 16)
    proj_kernel<<<pgrid, 256, PROJ_SMEM_BYTES>>>(xh, xl, wqh, wql,
                                                 nullptr, qh, ql, 1, 0.125f);
    proj_kernel<<<pgrid, 256, PROJ_SMEM_BYTES>>>(xh, xl, wkh, wkl,
                                                 nullptr, kh, kl, 1, 1.0f);
    proj_kernel<<<pgrid, 256, PROJ_SMEM_BYTES>>>(xh, xl, wvh, wvl,
                                                 nullptr, vth, vtl, 2, 1.0f);

    dim3 agrid(SEQ / 64, HEADS, BATCH);      // (32, 16, 4)
    attn_kernel<<<agrid, 128, ATTN_SMEM_BYTES>>>();

    proj_kernel<<<pgrid, 256, PROJ_SMEM_BYTES>>>(aoh, aol, woh, wol,
                                                 (float*)d_out, nullptr, nullptr,
                                                 0, 1.0f);
}

// round 17
// speedup vs baseline: 1.7677x; 1.7677x over previous
#include <cuda_runtime.h>
#include <cuda_bf16.h>
#include <cstdint>

// ---------------------------------------------------------------------------
// Causal MHA: B=4, S=2048, D=1024, H=16, Dh=64.  fp32 in/out.
// Projections: tf32x1 mma.m16n8k8 (operands rna-rounded to tf32) — 0.67x the
// MMA instructions of bf16x3; empirically instruction-count-bound.
// Attention: bf16x3 flash kernel (register PV), unchanged from R12.
// ---------------------------------------------------------------------------

#define DEV_INLINE __device__ __forceinline__

static constexpr int BATCH = 4;
static constexpr int SEQ   = 2048;
static constexpr int DMODEL = 1024;
static constexpr int HEADS = 16;
static constexpr int HDIM  = 64;
static constexpr int MROWS = BATCH * SEQ;          // 8192

// ---- scratch (__device__ globals; no cudaMalloc allowed) ----
__device__ float g_x [MROWS * DMODEL];              // tf32-rounded x
__device__ float g_wq[DMODEL * DMODEL], g_wk[DMODEL * DMODEL];
__device__ float g_wv[DMODEL * DMODEL], g_wo[DMODEL * DMODEL];
// Q,K packed bf16 hi/lo [bh][s][32 words] (Q has 0.125 baked in)
__device__ unsigned g_Qh[64 * SEQ * 32], g_Ql[64 * SEQ * 32];
__device__ unsigned g_Kh[64 * SEQ * 32], g_Kl[64 * SEQ * 32];
// V transposed [bh][dh][s] bf16 hi/lo
__device__ unsigned g_Vth[64 * HDIM * (SEQ / 2)], g_Vtl[64 * HDIM * (SEQ / 2)];
// attention out, fp32 (tf32-rounded) [b*2048+s][1024]
__device__ float g_AO[MROWS * DMODEL];

// ---------------------------------------------------------------------------
// helpers
// ---------------------------------------------------------------------------
DEV_INLINE unsigned f2tf(float x) {
    unsigned u;
    asm("cvt.rna.tf32.f32 %0, %1;" : "=r"(u) : "f"(x));
    return u;
}
DEV_INLINE unsigned fu(float x) { return __float_as_uint(x); }
DEV_INLINE unsigned pack2(float x0, float x1) {   // x0 -> low half
    unsigned r;
    asm("cvt.rn.bf16x2.f32 %0, %1, %2;" : "=r"(r) : "f"(x1), "f"(x0));
    return r;
}
DEV_INLINE void split_pack(float x0, float x1, unsigned& wh, unsigned& wl) {
    wh = pack2(x0, x1);
    float h0 = __uint_as_float(wh << 16);
    float h1 = __uint_as_float(wh & 0xffff0000u);
    wl = pack2(x0 - h0, x1 - h1);
}
DEV_INLINE unsigned cvta_s(const void* p) {
    return (unsigned)__cvta_generic_to_shared(p);
}
DEV_INLINE void ldsm4(unsigned& r0, unsigned& r1, unsigned& r2, unsigned& r3,
                      unsigned addr) {
    asm volatile("ldmatrix.sync.aligned.m8n8.x4.shared.b16 {%0,%1,%2,%3}, [%4];"
                 : "=r"(r0), "=r"(r1), "=r"(r2), "=r"(r3) : "r"(addr));
}
// tf32 m16n8k8
DEV_INLINE void mma8(float* d,
                     unsigned a0, unsigned a1, unsigned a2, unsigned a3,
                     unsigned b0, unsigned b1) {
    asm volatile(
        "mma.sync.aligned.m16n8k8.row.col.f32.tf32.tf32.f32 "
        "{%0,%1,%2,%3},{%4,%5,%6,%7},{%8,%9},{%0,%1,%2,%3};\n"
        : "+f"(d[0]), "+f"(d[1]), "+f"(d[2]), "+f"(d[3])
        : "r"(a0), "r"(a1), "r"(a2), "r"(a3), "r"(b0), "r"(b1));
}
// bf16 m16n8k16
DEV_INLINE void mma16(float* d,
                      unsigned a0, unsigned a1, unsigned a2, unsigned a3,
                      unsigned b0, unsigned b1) {
    asm volatile(
        "mma.sync.aligned.m16n8k16.row.col.f32.bf16.bf16.f32 "
        "{%0,%1,%2,%3},{%4,%5,%6,%7},{%8,%9},{%0,%1,%2,%3};\n"
        : "+f"(d[0]), "+f"(d[1]), "+f"(d[2]), "+f"(d[3])
        : "r"(a0), "r"(a1), "r"(a2), "r"(a3), "r"(b0), "r"(b1));
}
DEV_INLINE void cp16(unsigned dst_s, const void* src) {
    asm volatile("cp.async.cg.shared.global [%0], [%1], 16;"
                 :: "r"(dst_s), "l"(src));
}
DEV_INLINE void cp_commit() { asm volatile("cp.async.commit_group;"); }
template <int N> DEV_INLINE void cp_wait() {
    asm volatile("cp.async.wait_group %0;" :: "n"(N));
}

// ---------------------------------------------------------------------------
// Convert: fp32 -> tf32-rounded fp32 (rna)
// ---------------------------------------------------------------------------
__global__ void convert_tf32(const float4* __restrict__ src,
                             float4* __restrict__ dst, int n4) {
    int i = blockIdx.x * blockDim.x + threadIdx.x;
    if (i < n4) {
        float4 v = src[i];
        v.x = __uint_as_float(f2tf(v.x));
        v.y = __uint_as_float(f2tf(v.y));
        v.z = __uint_as_float(f2tf(v.z));
        v.w = __uint_as_float(f2tf(v.w));
        dst[i] = v;
    }
}

// ---------------------------------------------------------------------------
// tf32x1 projection GEMM: out[m][n] = sum_k A[m][k] * W[n][k]
// A, W pre-rounded to tf32.  CTA 128x64, BK=32, 8 warps (4x2, warp 32x32).
// 2-stage cp.async pipeline, fp32 smem pitch 36 (R3-proven frag math).
// mode 0: fp32 [m][1024];  mode 1: packed bf16 hi/lo [bh][s][32w] (*scale);
// mode 2: V transposed bf16 hi/lo [bh][dh][s].
// ---------------------------------------------------------------------------
static constexpr int P_PA  = 36;                         // floats per 32f row
static constexpr int P_STG = (128 + 64) * P_PA;          // 6912 floats/stage
static constexpr int PROJ_SMEM_BYTES = 2 * P_STG * 4;    // 55296

__global__ __launch_bounds__(256, 3)
void proj_kernel(const float* __restrict__ A, const float* __restrict__ W,
                 float* __restrict__ dst_f,
                 unsigned* __restrict__ dst_hi, unsigned* __restrict__ dst_lo,
                 int mode, float scale) {
    extern __shared__ float smf[];

    const int m0 = blockIdx.x * 128;
    const int n0 = blockIdx.y * 64;
    const int tid = threadIdx.x;
    const int warp = tid >> 5, lane = tid & 31;
    const int wm = warp & 3;    // 0..3  (32 rows each)
    const int wn = warp >> 2;   // 0..1  (32 cols each)

    const unsigned smB = cvta_s(smf);

    float acc[2][4][4];
#pragma unroll
    for (int mi = 0; mi < 2; mi++)
#pragma unroll
        for (int ni = 0; ni < 4; ni++)
#pragma unroll
            for (int j = 0; j < 4; j++) acc[mi][ni][j] = 0.0f;

    // load one stage: A 1024 chunks + B 512 chunks of 16B, 6 per thread
    auto prefetch = [&](int kt, int st) {
        unsigned base = (unsigned)(st * P_STG);
        int k0 = kt * 32;
#pragma unroll
        for (int i = 0; i < 4; i++) {                 // A rows
            int id = tid + i * 256;                   // 0..1023
            int row = id >> 3, c = (id & 7) * 4;
            cp16(smB + (base + row * P_PA + c) * 4u,
                 A + (size_t)(m0 + row) * DMODEL + k0 + c);
        }
#pragma unroll
        for (int i = 0; i < 2; i++) {                 // B rows
            int id = tid + i * 256;                   // 0..511
            int row = id >> 3, c = (id & 7) * 4;
            cp16(smB + (base + 128 * P_PA + row * P_PA + c) * 4u,
                 W + (size_t)(n0 + row) * DMODEL + k0 + c);
        }
    };

    prefetch(0, 0);
    cp_commit();

    for (int kt = 0; kt < 32; kt++) {
        const int st = kt & 1;
        cp_wait<0>();
        __syncthreads();
        if (kt + 1 < 32) {
            prefetch(kt + 1, st ^ 1);
            cp_commit();
        }

        const float* As = smf + st * P_STG;
        const float* Bs = As + 128 * P_PA;

#pragma unroll
        for (int kk = 0; kk < 4; kk++) {
            unsigned a[2][4];
#pragma unroll
            for (int mi = 0; mi < 2; mi++) {
                int ab = (wm * 32 + mi * 16 + (lane >> 2)) * P_PA
                       + kk * 8 + (lane & 3);
                a[mi][0] = fu(As[ab]);
                a[mi][1] = fu(As[ab + 8 * P_PA]);
                a[mi][2] = fu(As[ab + 4]);
                a[mi][3] = fu(As[ab + 8 * P_PA + 4]);
            }
#pragma unroll
            for (int ni = 0; ni < 4; ni++) {
                int colb = wn * 32 + ni * 8 + (lane >> 2);
                int bb = colb * P_PA + kk * 8 + (lane & 3);
                unsigned b0 = fu(Bs[bb]), b1 = fu(Bs[bb + 4]);
                mma8(acc[0][ni], a[0][0], a[0][1], a[0][2], a[0][3], b0, b1);
                mma8(acc[1][ni], a[1][0], a[1][1], a[1][2], a[1][3], b0, b1);
            }
        }
    }

    // ---- epilogue (R3-proven mapping) ----
#pragma unroll
    for (int mi = 0; mi < 2; mi++) {
#pragma unroll
        for (int ni = 0; ni < 4; ni++) {
            int r0 = m0 + wm * 32 + mi * 16 + (lane >> 2);
            int r1 = r0 + 8;
            int c0 = n0 + wn * 32 + ni * 8 + 2 * (lane & 3);
            if (mode == 0) {
                dst_f[(size_t)r0 * DMODEL + c0]     = acc[mi][ni][0];
                dst_f[(size_t)r0 * DMODEL + c0 + 1] = acc[mi][ni][1];
                dst_f[(size_t)r1 * DMODEL + c0]     = acc[mi][ni][2];
                dst_f[(size_t)r1 * DMODEL + c0 + 1] = acc[mi][ni][3];
            } else if (mode == 1) {
                int h = c0 >> 6, dhw = (c0 & 63) >> 1;
                unsigned wh, wl;
                {
                    int b = r0 >> 11, s = r0 & 2047;
                    size_t idx = ((size_t)(b * HEADS + h) * SEQ + s) * 32 + dhw;
                    split_pack(acc[mi][ni][0] * scale, acc[mi][ni][1] * scale, wh, wl);
                    dst_hi[idx] = wh; dst_lo[idx] = wl;
                }
                {
                    int b = r1 >> 11, s = r1 & 2047;
                    size_t idx = ((size_t)(b * HEADS + h) * SEQ + s) * 32 + dhw;
                    split_pack(acc[mi][ni][2] * scale, acc[mi][ni][3] * scale, wh, wl);
                    dst_hi[idx] = wh; dst_lo[idx] = wl;
                }
            } else {
                __nv_bfloat16* vh = reinterpret_cast<__nv_bfloat16*>(dst_hi);
                __nv_bfloat16* vl = reinterpret_cast<__nv_bfloat16*>(dst_lo);
#pragma unroll
                for (int e = 0; e < 4; e++) {
                    int r = (e < 2) ? r0 : r1;
                    int c = c0 + (e & 1);
                    float v = acc[mi][ni][e];
                    int b = r >> 11, s = r & 2047;
                    int h = c >> 6, dh = c & 63;
                    size_t idx = ((size_t)(b * HEADS + h) * HDIM + dh) * SEQ + s;
                    __nv_bfloat16 hb = __float2bfloat16(v);
                    vh[idx] = hb;
                    vl[idx] = __float2bfloat16(v - __bfloat162float(hb));
                }
            }
        }
    }
}

// ---------------------------------------------------------------------------
// Flash attention: CTA = (64-row q tile, head, batch), 4 warps, 3 CTAs/SM.
// Score: bf16x3 k16.  PV: bf16x3 k16, P-frags from regs (R12, known-good).
// Epilogue writes tf32-rounded fp32 AO.
// ---------------------------------------------------------------------------
static constexpr int A_PW = 36;
static constexpr int AT_Q = 0;
static constexpr int AT_K = 4608;
static constexpr int AT_V = 13824;
static constexpr int ATTN_SMEM_BYTES = 18432 * 4;    // 73728

__global__ __launch_bounds__(128, 3)
void attn_kernel() {
    extern __shared__ unsigned smw[];
    const unsigned smB = cvta_s(smw);

    const int qt = (int)(gridDim.x - 1) - (int)blockIdx.x;
    const int h = blockIdx.y;
    const int b = blockIdx.z;
    const int bh = b * HEADS + h;
    const int q0 = qt * 64;

    const int tid = threadIdx.x;
    const int warp = tid >> 5;
    const int lane = tid & 31;

    const int a_row_off  = (lane & 7) + ((lane >> 3) & 1) * 8;
    const int a_word_off = ((lane >> 4) & 1) * 4;
    const int b_row_off  = (lane & 7) + ((lane >> 4) & 1) * 8;
    const int b_word_off = ((lane >> 3) & 1) * 4;

    const unsigned qOff = ((16 * warp + a_row_off) * A_PW + a_word_off) * 4u;
    unsigned kOff[4];
#pragma unroll
    for (int p = 0; p < 4; p++)
        kOff[p] = ((p * 16 + b_row_off) * A_PW + b_word_off) * 4u;

    auto issueQ = [&]() {
#pragma unroll
        for (int i = 0; i < 8; i++) {
            int ch = tid + i * 128;
            int row = ch >> 4, sub = ch & 15;
            int buf = sub >> 3, w = (sub & 7) * 4;
            const unsigned* src = (buf ? g_Ql : g_Qh) +
                                  ((size_t)bh * SEQ + q0 + row) * 32 + w;
            cp16(smB + (AT_Q + (unsigned)buf * 2304u + row * A_PW + w) * 4u, src);
        }
    };
    auto issueK = [&](int j, int st) {
#pragma unroll
        for (int i = 0; i < 8; i++) {
            int ch = tid + i * 128;
            int row = ch >> 4, sub = ch & 15;
            int buf = sub >> 3, w = (sub & 7) * 4;
            const unsigned* src = (buf ? g_Kl : g_Kh) +
                                  ((size_t)bh * SEQ + j * 64 + row) * 32 + w;
            cp16(smB + (AT_K + (unsigned)st * 4608u + (unsigned)buf * 2304u +
                        row * A_PW + w) * 4u, src);
        }
    };
    auto issueV = [&](int j) {
#pragma unroll
        for (int i = 0; i < 8; i++) {
            int ch = tid + i * 128;
            int row = ch >> 4, sub = ch & 15;
            int buf = sub >> 3, w = (sub & 7) * 4;
            const unsigned* src = (buf ? g_Vtl : g_Vth) +
                                  ((size_t)bh * HDIM + row) * (SEQ / 2) + j * 32 + w;
            cp16(smB + (AT_V + (unsigned)buf * 2304u + row * A_PW + w) * 4u, src);
        }
    };

    issueQ();
    issueK(0, 0);
    cp_commit();

    const float NEG = -1e30f;
    float mr0 = NEG, mr1 = NEG, l0 = 0.0f, l1 = 0.0f;
    float o[8][4];
#pragma unroll
    for (int nc = 0; nc < 8; nc++)
#pragma unroll
        for (int j = 0; j < 4; j++) o[nc][j] = 0.0f;

    const unsigned QhB = smB + AT_Q * 4u, QlB = QhB + 2304u * 4u;
    const unsigned VhB = smB + AT_V * 4u, VlB = VhB + 2304u * 4u;

    for (int j = 0; j <= qt; j++) {
        const int st = j & 1;
        const bool more = (j < qt);

        issueV(j);
        cp_commit();
        if (more) {
            issueK(j + 1, st ^ 1);
            cp_commit();
            cp_wait<2>();
        } else {
            cp_wait<1>();
        }
        __syncthreads();

        const unsigned KhB = smB + (AT_K + (unsigned)st * 4608u) * 4u;
        const unsigned KlB = KhB + 2304u * 4u;

        float s[8][4];
#pragma unroll
        for (int nc = 0; nc < 8; nc++)
#pragma unroll
            for (int e = 0; e < 4; e++) s[nc][e] = 0.0f;

#pragma unroll
        for (int kk = 0; kk < 4; kk++) {
            unsigned ah0, ah1, ah2, ah3, al0, al1, al2, al3;
            ldsm4(ah0, ah1, ah2, ah3, QhB + qOff + kk * 32u);
            ldsm4(al0, al1, al2, al3, QlB + qOff + kk * 32u);
#pragma unroll
            for (int p = 0; p < 4; p++) {
                unsigned kh0, kh1, kh2, kh3, kl0, kl1, kl2, kl3;
                ldsm4(kh0, kh1, kh2, kh3, KhB + kOff[p] + kk * 32u);
                ldsm4(kl0, kl1, kl2, kl3, KlB + kOff[p] + kk * 32u);
                mma16(s[2 * p],     ah0, ah1, ah2, ah3, kh0, kh1);
                mma16(s[2 * p],     al0, al1, al2, al3, kh0, kh1);
                mma16(s[2 * p],     ah0, ah1, ah2, ah3, kl0, kl1);
                mma16(s[2 * p + 1], ah0, ah1, ah2, ah3, kh2, kh3);
                mma16(s[2 * p + 1], al0, al1, al2, al3, kh2, kh3);
                mma16(s[2 * p + 1], ah0, ah1, ah2, ah3, kl2, kl3);
            }
        }

        if (j == qt) {
            int r0 = 16 * warp + (lane >> 2), r1 = r0 + 8;
#pragma unroll
            for (int nc = 0; nc < 8; nc++) {
                int c0 = nc * 8 + 2 * (lane & 3), c1 = c0 + 1;
                if (c0 > r0) s[nc][0] = NEG;
                if (c1 > r0) s[nc][1] = NEG;
                if (c0 > r1) s[nc][2] = NEG;
                if (c1 > r1) s[nc][3] = NEG;
            }
        }

        float pm0 = NEG, pm1 = NEG;
#pragma unroll
        for (int nc = 0; nc < 8; nc++) {
            pm0 = fmaxf(pm0, fmaxf(s[nc][0], s[nc][1]));
            pm1 = fmaxf(pm1, fmaxf(s[nc][2], s[nc][3]));
        }
        pm0 = fmaxf(pm0, __shfl_xor_sync(0xffffffffu, pm0, 1));
        pm0 = fmaxf(pm0, __shfl_xor_sync(0xffffffffu, pm0, 2));
        pm1 = fmaxf(pm1, __shfl_xor_sync(0xffffffffu, pm1, 1));
        pm1 = fmaxf(pm1, __shfl_xor_sync(0xffffffffu, pm1, 2));

        float mn0 = fmaxf(mr0, pm0), mn1 = fmaxf(mr1, pm1);
        float al0 = __expf(mr0 - mn0), al1 = __expf(mr1 - mn1);
        l0 *= al0;
        l1 *= al1;

        float rs0 = 0.0f, rs1 = 0.0f;
#pragma unroll
        for (int nc = 0; nc < 8; nc++) {
            s[nc][0] = __expf(s[nc][0] - mn0);
            s[nc][1] = __expf(s[nc][1] - mn0);
            s[nc][2] = __expf(s[nc][2] - mn1);
            s[nc][3] = __expf(s[nc][3] - mn1);
            rs0 += s[nc][0] + s[nc][1];
            rs1 += s[nc][2] + s[nc][3];
            o[nc][0] *= al0; o[nc][1] *= al0;
            o[nc][2] *= al1; o[nc][3] *= al1;
        }
        rs0 += __shfl_xor_sync(0xffffffffu, rs0, 1);
        rs0 += __shfl_xor_sync(0xffffffffu, rs0, 2);
        rs1 += __shfl_xor_sync(0xffffffffu, rs1, 1);
        rs1 += __shfl_xor_sync(0xffffffffu, rs1, 2);
        l0 += rs0;
        l1 += rs1;
        mr0 = mn0;
        mr1 = mn1;

        if (more) cp_wait<1>(); else cp_wait<0>();
        __syncthreads();

#pragma unroll
        for (int kc = 0; kc < 4; kc++) {
            unsigned pah[4], pal[4];
            split_pack(s[2 * kc][0],     s[2 * kc][1],     pah[0], pal[0]);
            split_pack(s[2 * kc][2],     s[2 * kc][3],     pah[1], pal[1]);
            split_pack(s[2 * kc + 1][0], s[2 * kc + 1][1], pah[2], pal[2]);
            split_pack(s[2 * kc + 1][2], s[2 * kc + 1][3], pah[3], pal[3]);
#pragma unroll
            for (int p = 0; p < 4; p++) {
                unsigned vh0, vh1, vh2, vh3, vl0, vl1, vl2, vl3;
                ldsm4(vh0, vh1, vh2, vh3, VhB + kOff[p] + kc * 32u);
                ldsm4(vl0, vl1, vl2, vl3, VlB + kOff[p] + kc * 32u);
                mma16(o[2 * p],     pah[0], pah[1], pah[2], pah[3], vh0, vh1);
                mma16(o[2 * p],     pal[0], pal[1], pal[2], pal[3], vh0, vh1);
                mma16(o[2 * p],     pah[0], pah[1], pah[2], pah[3], vl0, vl1);
                mma16(o[2 * p + 1], pah[0], pah[1], pah[2], pah[3], vh2, vh3);
                mma16(o[2 * p + 1], pal[0], pal[1], pal[2], pal[3], vh2, vh3);
                mma16(o[2 * p + 1], pah[0], pah[1], pah[2], pah[3], vl2, vl3);
            }
        }
        __syncthreads();
    }

    // epilogue: normalize, tf32-round, write fp32 AO [b*2048+s][h*64+dh]
    float inv0 = 1.0f / l0, inv1 = 1.0f / l1;
    int r0g = q0 + 16 * warp + (lane >> 2);
    int r1g = r0g + 8;
#pragma unroll
    for (int nc = 0; nc < 8; nc++) {
        int col = h * HDIM + nc * 8 + 2 * (lane & 3);
        size_t i0 = ((size_t)(b * SEQ + r0g)) * DMODEL + col;
        size_t i1 = ((size_t)(b * SEQ + r1g)) * DMODEL + col;
        g_AO[i0]     = __uint_as_float(f2tf(o[nc][0] * inv0));
        g_AO[i0 + 1] = __uint_as_float(f2tf(o[nc][1] * inv0));
        g_AO[i1]     = __uint_as_float(f2tf(o[nc][2] * inv1));
        g_AO[i1 + 1] = __uint_as_float(f2tf(o[nc][3] * inv1));
    }
}

// ---------------------------------------------------------------------------
extern "C" void kernel_launch(void* const* d_in, const int* in_sizes, int n_in,
                              void* d_out, int out_size) {
    const float* x  = (const float*)d_in[0];
    const float* wq = (const float*)d_in[1];
    const float* wk = (const float*)d_in[2];
    const float* wv = (const float*)d_in[3];
    const float* wo = (const float*)d_in[4];

    float *gx, *gwq, *gwk, *gwv, *gwo, *gao;
    unsigned *qh, *ql, *kh, *kl, *vth, *vtl;
    cudaGetSymbolAddress((void**)&gx,  g_x);
    cudaGetSymbolAddress((void**)&gwq, g_wq);
    cudaGetSymbolAddress((void**)&gwk, g_wk);
    cudaGetSymbolAddress((void**)&gwv, g_wv);
    cudaGetSymbolAddress((void**)&gwo, g_wo);
    cudaGetSymbolAddress((void**)&gao, g_AO);
    cudaGetSymbolAddress((void**)&qh,  g_Qh);  cudaGetSymbolAddress((void**)&ql,  g_Ql);
    cudaGetSymbolAddress((void**)&kh,  g_Kh);  cudaGetSymbolAddress((void**)&kl,  g_Kl);
    cudaGetSymbolAddress((void**)&vth, g_Vth); cudaGetSymbolAddress((void**)&vtl, g_Vtl);

    cudaFuncSetAttribute(proj_kernel, cudaFuncAttributeMaxDynamicSharedMemorySize,
                         PROJ_SMEM_BYTES);
    cudaFuncSetAttribute(attn_kernel, cudaFuncAttributeMaxDynamicSharedMemorySize,
                         ATTN_SMEM_BYTES);

    const int N4_X = MROWS * DMODEL / 4;    // 2097152
    const int N4_W = DMODEL * DMODEL / 4;   // 262144
    convert_tf32<<<N4_X / 256, 256>>>((const float4*)x,  (float4*)gx,  N4_X);
    convert_tf32<<<N4_W / 256, 256>>>((const float4*)wq, (float4*)gwq, N4_W);
    convert_tf32<<<N4_W / 256, 256>>>((const float4*)wk, (float4*)gwk, N4_W);
    convert_tf32<<<N4_W / 256, 256>>>((const float4*)wv, (float4*)gwv, N4_W);
    convert_tf32<<<N4_W / 256, 256>>>((const float4*)wo, (float4*)gwo, N4_W);

    dim3 pgrid(MROWS / 128, DMODEL / 64);    // (64, 16)
    proj_kernel<<<pgrid, 256, PROJ_SMEM_BYTES>>>(gx, gwq,
                                                 nullptr, qh, ql, 1, 0.125f);
    proj_kernel<<<pgrid, 256, PROJ_SMEM_BYTES>>>(gx, gwk,
                                                 nullptr, kh, kl, 1, 1.0f);
    proj_kernel<<<pgrid, 256, PROJ_SMEM_BYTES>>>(gx, gwv,
                                                 nullptr, vth, vtl, 2, 1.0f);

    dim3 agrid(SEQ / 64, HEADS, BATCH);      // (32, 16, 4)
    attn_kernel<<<agrid, 128, ATTN_SMEM_BYTES>>>();

    proj_kernel<<<pgrid, 256, PROJ_SMEM_BYTES>>>(gao, gwo,
                                                 (float*)d_out, nullptr, nullptr,
                                                 0, 1.0f);
}